// round 6
// baseline (speedup 1.0000x reference)
#include <cuda_runtime.h>
#include <cstdint>

#define SZ 512
#define SLAB 128
#define NPLANES 256

// cross-block scratch (allocation-free: __device__ globals)
__device__ float g_colsum[NPLANES][4][SZ];
__device__ float g_snapM[NPLANES][SZ];
__device__ float g_snapA[NPLANES][SZ];
__device__ float g_RT[NPLANES][SZ];
__device__ float g_PM[NPLANES][SZ];
__device__ float g_PA[NPLANES][SZ];
__device__ float g_DA[NPLANES][SZ];
__device__ unsigned int g_cnt[NPLANES];   // zero-init; self-reset each launch

__device__ __forceinline__ uint64_t pack2(float lo, float hi) {
    uint64_t d;
    asm("mov.b64 %0, {%1, %2};" : "=l"(d) : "f"(lo), "f"(hi));
    return d;
}
__device__ __forceinline__ void unpack2(uint64_t d, float& lo, float& hi) {
    asm("mov.b64 {%0, %1}, %2;" : "=f"(lo), "=f"(hi) : "l"(d));
}
__device__ __forceinline__ uint64_t addf32x2(uint64_t a, uint64_t b) {
    uint64_t d;
    asm("add.rn.f32x2 %0, %1, %2;" : "=l"(d) : "l"(a), "l"(b));
    return d;
}

// Reduce 8 independent per-lane values over the warp in 9 shuffles.
// Lane L ends holding the full 32-lane sum of value (L & 7).
__device__ __forceinline__ float multireduce8(const float* v, int lane) {
    const unsigned F = 0xffffffffu;
    const bool b0 = lane & 1;
    float x01 = (b0 ? v[1] : v[0]) + __shfl_xor_sync(F, b0 ? v[0] : v[1], 1);
    float x23 = (b0 ? v[3] : v[2]) + __shfl_xor_sync(F, b0 ? v[2] : v[3], 1);
    float x45 = (b0 ? v[5] : v[4]) + __shfl_xor_sync(F, b0 ? v[4] : v[5], 1);
    float x67 = (b0 ? v[7] : v[6]) + __shfl_xor_sync(F, b0 ? v[6] : v[7], 1);
    const bool b1 = lane & 2;
    float y03 = (b1 ? x23 : x01) + __shfl_xor_sync(F, b1 ? x01 : x23, 2);
    float y47 = (b1 ? x67 : x45) + __shfl_xor_sync(F, b1 ? x45 : x67, 2);
    const bool b2 = lane & 4;
    float z = (b2 ? y47 : y03) + __shfl_xor_sync(F, b2 ? y03 : y47, 4);
    z += __shfl_xor_sync(F, z, 8);
    z += __shfl_xor_sync(F, z, 16);
    return z;
}

__global__ __launch_bounds__(512, 1)
void slab_kernel(const float* __restrict__ x, float* __restrict__ out) {
    __shared__ float sBandRow[4][SLAB];
    __shared__ float sColPart[4][SZ];
    __shared__ float sCutM[SLAB];
    __shared__ float sCutA[SLAB];
    __shared__ float sSnapM[SLAB];
    __shared__ float sSnapA[SLAB];
    __shared__ float sDA[SLAB];
    __shared__ float cA1[SZ], cA2[SZ], cCT[SZ], cRT[SZ], cPM[SZ], cPA[SZ], cDAo[SZ];
    __shared__ bool amLast;

    const int blk = blockIdx.x;
    const int p = blk >> 2;
    const int s = blk & 3;
    const float* __restrict__ X = x + ((size_t)p * SZ + (size_t)s * SLAB) * SZ;

    const int tid  = threadIdx.x;
    const int w    = tid >> 5;
    const int lane = tid & 31;
    const int wr = w >> 2, wc = w & 3;
    const int c0  = wc * 128;
    const int lr0 = wr * 32;
    const bool mainRole = (wc == s);
    const bool antiRole = (wc == 3 - s);

    const float4* __restrict__ base =
        reinterpret_cast<const float4*>(X + (size_t)lr0 * SZ + c0) + lane;
    const int RS4 = SZ / 4;

    uint64_t acc01 = 0ull, acc23 = 0ull;

    // prime pipeline: group 0 in flight
    float4 v[8];
#pragma unroll
    for (int u = 0; u < 8; u++)
        v[u] = __ldcs(base + u * RS4);

#pragma unroll
    for (int g = 0; g < 4; ++g) {
        // prefetch next group while this one's reduce chains run
        float4 n[8];
        if (g < 3) {
#pragma unroll
            for (int u = 0; u < 8; u++)
                n[u] = __ldcs(base + ((g + 1) * 8 + u) * RS4);
        }

        const int lrg = lr0 + 8 * g;

        float sv[8];
#pragma unroll
        for (int u = 0; u < 8; u++) {
            uint64_t h = addf32x2(pack2(v[u].x, v[u].y), pack2(v[u].z, v[u].w));
            float lo, hi; unpack2(h, lo, hi);
            sv[u] = lo + hi;
        }

        const float r8 = multireduce8(sv, lane);
        if (lane < 8) sBandRow[wc][lrg + lane] = r8;

        if (mainRole) {
            const int ls0 = 8 * wr + 2 * g;
            float m[8];
            {
                const bool lt = lane < ls0, eq = lane == ls0;
                m[0] = lt ? sv[0] : eq ? v[0].x : 0.f;
                m[1] = lt ? sv[1] : eq ? (v[1].x + v[1].y) : 0.f;
                m[2] = lt ? sv[2] : eq ? ((v[2].x + v[2].y) + v[2].z) : 0.f;
                m[3] = (lt | eq) ? sv[3] : 0.f;
            }
            {
                const int ls1 = ls0 + 1;
                const bool lt = lane < ls1, eq = lane == ls1;
                m[4] = lt ? sv[4] : eq ? v[4].x : 0.f;
                m[5] = lt ? sv[5] : eq ? (v[5].x + v[5].y) : 0.f;
                m[6] = lt ? sv[6] : eq ? ((v[6].x + v[6].y) + v[6].z) : 0.f;
                m[7] = (lt | eq) ? sv[7] : 0.f;
            }
            const float mc = multireduce8(m, lane);
            if (lane < 8) sCutM[lrg + lane] = mc;
        }
        if (antiRole) {
            const int lsA0 = (127 - lrg) >> 2;
            float m[8];
            {
                const bool lt = lane < lsA0, eq = lane == lsA0;
                m[0] = (lt | eq) ? sv[0] : 0.f;
                m[1] = lt ? sv[1] : eq ? ((v[1].x + v[1].y) + v[1].z) : 0.f;
                m[2] = lt ? sv[2] : eq ? (v[2].x + v[2].y) : 0.f;
                m[3] = lt ? sv[3] : eq ? v[3].x : 0.f;
            }
            {
                const int lsA1 = lsA0 - 1;
                const bool lt = lane < lsA1, eq = lane == lsA1;
                m[4] = (lt | eq) ? sv[4] : 0.f;
                m[5] = lt ? sv[5] : eq ? ((v[5].x + v[5].y) + v[5].z) : 0.f;
                m[6] = lt ? sv[6] : eq ? (v[6].x + v[6].y) : 0.f;
                m[7] = lt ? sv[7] : eq ? v[7].x : 0.f;
            }
            const float mc = multireduce8(m, lane);
            if (lane < 8) sCutA[lrg + lane] = mc;
        }

        // snapshots (strict col prefixes, read acc BEFORE update) + packed acc update
#pragma unroll
        for (int u = 0; u < 8; u++) {
            const int lr = lrg + u;
            if (mainRole) {
                const int ls = 8 * wr + 2 * g + (u >> 2);
                if (lane == ls) {
                    float lo, hi, sn;
                    if ((u & 3) < 2) { unpack2(acc01, lo, hi); sn = ((u & 3) == 0) ? lo : hi; }
                    else             { unpack2(acc23, lo, hi); sn = ((u & 3) == 2) ? lo : hi; }
                    sSnapM[lr] = sn;
                }
            }
            if (antiRole) {
                const int lsA = ((127 - lrg) >> 2) - (u >> 2);
                const int kA = 3 - (u & 3);
                if (lane == lsA) {
                    const float e = (kA == 0) ? v[u].x : (kA == 1) ? v[u].y
                                  : (kA == 2) ? v[u].z : v[u].w;
                    float lo, hi, sn;
                    if (kA < 2) { unpack2(acc01, lo, hi); sn = (kA == 0) ? lo : hi; }
                    else        { unpack2(acc23, lo, hi); sn = (kA == 2) ? lo : hi; }
                    sSnapA[127 - lr] = sn;
                    sDA[lr] = e;
                }
            }
            acc01 = addf32x2(acc01, pack2(v[u].x, v[u].y));
            acc23 = addf32x2(acc23, pack2(v[u].z, v[u].w));
        }

        if (g < 3) {
#pragma unroll
            for (int u = 0; u < 8; u++) v[u] = n[u];
        }
    }

    {
        float a0, a1, a2, a3;
        unpack2(acc01, a0, a1);
        unpack2(acc23, a2, a3);
        reinterpret_cast<float4*>(&sColPart[wr][c0])[lane] = make_float4(a0, a1, a2, a3);
    }
    __syncthreads();

    // ---- slab combine: columns ----
    {
        const int c = tid;
        const float q0 = sColPart[0][c], q1 = sColPart[1][c],
                    q2 = sColPart[2][c], q3 = sColPart[3][c];
        g_colsum[p][s][c] = (q0 + q1) + (q2 + q3);

        const int band = c >> 7;
        if (band == s) {
            const int lr = c - 128 * s;
            const int rg = lr >> 5;
            float sn = sSnapM[lr];
            if (rg > 0) sn += q0;
            if (rg > 1) sn += q1;
            if (rg > 2) sn += q2;
            g_snapM[p][c] = sn;
        }
        if (band == 3 - s) {
            const int la = c - 128 * (3 - s);   // == 127 - lr
            const int rg = (127 - la) >> 5;
            float sn = sSnapA[la];
            if (rg > 0) sn += q0;
            if (rg > 1) sn += q1;
            if (rg > 2) sn += q2;
            g_snapA[p][c] = sn;
        }
    }
    // ---- slab combine: rows ----
    if (tid < SLAB) {
        const int lr = tid;
        const int gr = 128 * s + lr;
        const float b0 = sBandRow[0][lr], b1 = sBandRow[1][lr],
                    b2 = sBandRow[2][lr], b3 = sBandRow[3][lr];
        g_RT[p][gr] = (b0 + b1) + (b2 + b3);

        float pm = sCutM[lr];
        if (s > 0) pm += b0;
        if (s > 1) pm += b1;
        if (s > 2) pm += b2;
        g_PM[p][gr] = pm;

        const int ab = 3 - s;
        float pa = sCutA[lr];
        if (ab > 0) pa += b0;
        if (ab > 1) pa += b1;
        if (ab > 2) pa += b2;
        g_PA[p][gr] = pa;

        g_DA[p][gr] = sDA[lr];
    }

    // ---- last-block-per-plane fused combine ----
    __threadfence();
    __syncthreads();
    if (tid == 0) {
        const unsigned t = atomicAdd(&g_cnt[p], 1u);
        amLast = (t == 3u);
        if (amLast) g_cnt[p] = 0;
    }
    __syncthreads();
    if (!amLast) return;

    {
        const int i = tid;
        const float q0 = g_colsum[p][0][i], q1 = g_colsum[p][1][i],
                    q2 = g_colsum[p][2][i], q3 = g_colsum[p][3][i];
        cCT[i] = (q0 + q1) + (q2 + q3);

        const int jm = i >> 7;
        float a1 = g_snapM[p][i];
        if (jm > 0) a1 += q0;
        if (jm > 1) a1 += q1;
        if (jm > 2) a1 += q2;
        cA1[i] = a1;

        const int ja = (SZ - 1 - i) >> 7;
        float a2 = g_snapA[p][i];
        if (ja > 0) a2 += q0;
        if (ja > 1) a2 += q1;
        if (ja > 2) a2 += q2;
        cA2[i] = a2;

        cRT[i] = g_RT[p][i]; cPM[i] = g_PM[p][i]; cPA[i] = g_PA[p][i]; cDAo[i] = g_DA[p][i];
    }
    __syncthreads();
    {
        const int i = tid;
        const int m = SZ - 1 - i;

        const float tl = cPM[i] + cA1[i];
        const float tr = cRT[i] - cPA[i] + cDAo[i] + cA2[m];
        const float bl = cPA[m] + cCT[i] - cA2[i] - cDAo[m];
        const float br = cRT[m] - cPM[m] + cCT[m] - cA1[m];

        const float inv = 1.0f / (float)(2 * i + 1);
        const int b  = p >> 3;
        const int ch = p & 7;
        float* __restrict__ o = out + ((size_t)(b * SZ + i)) * 32 + ch;
        o[0]  = tl * inv;
        o[8]  = tr * inv;
        o[16] = bl * inv;
        o[24] = br * inv;
    }
}

extern "C" void kernel_launch(void* const* d_in, const int* in_sizes, int n_in,
                              void* d_out, int out_size) {
    const float* x = (const float*)d_in[0];
    float* out = (float*)d_out;
    const int planes = in_sizes[0] / (SZ * SZ);   // 256
    slab_kernel<<<planes * 4, 512>>>(x, out);
}